// round 5
// baseline (speedup 1.0000x reference)
#include <cuda_runtime.h>
#include <math.h>

#define S 48
#define BATCH 16
#define HID 512
#define HDIR 256
#define NL 16
#define M_ROWS 768            // S*BATCH
#define VOUT 32000

// ---------------- device scratch (static, no allocation) ----------------
__device__ float g_act0[M_ROWS * HID];
__device__ float g_act1[M_ROWS * HID];
__device__ float g_G[M_ROWS * 2048];
__device__ float g_hping[8192];
__device__ float g_hpong[8192];
__device__ float g_dech0[NL * 8192];
__device__ float g_decc0[NL * 8192];
// sync area: sense replicas at g_sync[i*256] (1KB stride -> distinct L2 slices),
// arrival counter at g_sync[4096]. All zero-initialized at module load.
__device__ unsigned g_sync[5120];

// ---------------- sense-reversing grid barrier (128 CTAs) ----------------
__device__ __forceinline__ void gbar(unsigned& ls) {
    unsigned tgt = ls ^ 1u;
    __syncthreads();
    if (threadIdx.x == 0) {
        unsigned old;
        unsigned one = 1u, zero = 0u;
        asm volatile("atom.release.gpu.add.u32 %0, [%1], %2;"
                     : "=r"(old) : "l"(&g_sync[4096]), "r"(one) : "memory");
        if (old == 127u) {
            asm volatile("st.relaxed.gpu.u32 [%0], %1;" :: "l"(&g_sync[4096]), "r"(zero) : "memory");
#pragma unroll
            for (int i = 0; i < 16; ++i)
                asm volatile("st.release.gpu.u32 [%0], %1;" :: "l"(&g_sync[i * 256]), "r"(tgt) : "memory");
        } else {
            const unsigned* sp = &g_sync[(blockIdx.x & 15) * 256];
            unsigned s;
            do {
                asm volatile("ld.acquire.gpu.u32 %0, [%1];" : "=r"(s) : "l"(sp) : "memory");
            } while (s != tgt);
        }
    }
    __syncthreads();
    ls = tgt;
}

// ---------------- embedding gather ----------------
__global__ void embed_k(const float* __restrict__ emb, const int* __restrict__ ids,
                        float* __restrict__ out) {
    int tb = blockIdx.x;            // t*16+b
    int t = tb >> 4, b = tb & 15;
    int id = ids[b * S + t];
    const float4* src = reinterpret_cast<const float4*>(emb) + (size_t)id * (HID / 4);
    float4* dst = reinterpret_cast<float4*>(out) + (size_t)tb * (HID / 4);
    dst[threadIdx.x] = src[threadIdx.x];
}

// ---------------- C[m][n] = A[m][:512] . W[n][:512] + bias[n], M=768, K=512 ----------------
__global__ __launch_bounds__(256) void gemm_k(
    const float* __restrict__ A, const float* __restrict__ W,
    const float* __restrict__ bias, float* __restrict__ C,
    size_t sB, size_t sT, size_t sN) {
    __shared__ float4 smem4[(16 * 68 * 2) / 4];
    float* As = (float*)smem4;
    float* Ws = As + 16 * 68;
    int tid = threadIdx.x;
    int tx = tid & 15, ty = tid >> 4;
    int n0 = blockIdx.x * 64, m0 = blockIdx.y * 64;
    int r = tid >> 2, kq = (tid & 3) * 4;

    float acc[16];
#pragma unroll
    for (int i = 0; i < 16; ++i) acc[i] = 0.f;

    for (int k0 = 0; k0 < 512; k0 += 16) {
        float4 a = *reinterpret_cast<const float4*>(A + (size_t)(m0 + r) * 512 + k0 + kq);
        float4 w = *reinterpret_cast<const float4*>(W + (size_t)(n0 + r) * 512 + k0 + kq);
        As[(kq + 0) * 68 + r] = a.x; As[(kq + 1) * 68 + r] = a.y;
        As[(kq + 2) * 68 + r] = a.z; As[(kq + 3) * 68 + r] = a.w;
        Ws[(kq + 0) * 68 + r] = w.x; Ws[(kq + 1) * 68 + r] = w.y;
        Ws[(kq + 2) * 68 + r] = w.z; Ws[(kq + 3) * 68 + r] = w.w;
        __syncthreads();
#pragma unroll
        for (int kk = 0; kk < 16; ++kk) {
            float4 av = *reinterpret_cast<const float4*>(&As[kk * 68 + ty * 4]);
            float4 wv = *reinterpret_cast<const float4*>(&Ws[kk * 68 + tx * 4]);
            acc[0]  += av.x * wv.x; acc[1]  += av.x * wv.y; acc[2]  += av.x * wv.z; acc[3]  += av.x * wv.w;
            acc[4]  += av.y * wv.x; acc[5]  += av.y * wv.y; acc[6]  += av.y * wv.z; acc[7]  += av.y * wv.w;
            acc[8]  += av.z * wv.x; acc[9]  += av.z * wv.y; acc[10] += av.z * wv.z; acc[11] += av.z * wv.w;
            acc[12] += av.w * wv.x; acc[13] += av.w * wv.y; acc[14] += av.w * wv.z; acc[15] += av.w * wv.w;
        }
        __syncthreads();
    }
#pragma unroll
    for (int i = 0; i < 4; ++i) {
        int m = m0 + ty * 4 + i;
        int b = m & 15, t = m >> 4;
#pragma unroll
        for (int jx = 0; jx < 4; ++jx) {
            int n = n0 + tx * 4 + jx;
            C[(size_t)b * sB + (size_t)t * sT + (size_t)n * sN] = acc[i * 4 + jx] + bias[n];
        }
    }
}

__device__ __forceinline__ float sigm(float x) { return 1.f / (1.f + expf(-x)); }

// ======================= persistent decoder layer =======================
// 128 CTAs x 256 threads. CTA owns 4 j (x 4 gates = 16 rows of 2048).
__global__ __launch_bounds__(256, 1) void dec_layer_k(
    const float* __restrict__ Whh,             // (2048,512)
    const float* __restrict__ G, float* __restrict__ ds_out,
    float* __restrict__ hp, float* __restrict__ hq,
    const float* __restrict__ dh, const float* __restrict__ dc) {
    __shared__ float4 h4[2048];                // 32KB; overlaid by red/gsum after use
    __shared__ float c_sm[64];
    __shared__ unsigned s_sense;
    float* red = reinterpret_cast<float*>(h4); // [kc*256 + rid*16 + b]
    float* gsum = red + 4096;                  // 256 floats

    int tid = threadIdx.x;
    int kc = tid >> 4;
    int rid = tid & 15;
    int g = rid >> 2, jj = rid & 3;
    int j0 = blockIdx.x * 4;
    int row = g * 512 + j0 + jj;

    const float4* wp = reinterpret_cast<const float4*>(Whh + (size_t)row * 512 + kc * 32);
    float4 w[8];
#pragma unroll
    for (int i = 0; i < 8; ++i) w[i] = wp[i];

    int ujj = tid >> 4, ub = tid & 15;          // valid when tid<64
    int ujg = j0 + ujj;
    if (tid < 64) c_sm[tid] = dc[ub * 512 + ujg];
    if (tid == 0) {
        unsigned v;
        asm volatile("ld.relaxed.gpu.u32 %0, [%1];" : "=r"(v) : "l"(&g_sync[0]) : "memory");
        s_sense = v;
    }
    __syncthreads();
    unsigned ls = s_sense;

    float gi = 0.f, gf = 0.f, gg_ = 0.f, go = 0.f;
    if (tid < 64) {
        const float* Gp = G + (size_t)ub * 2048 + ujg;    // t = 0
        gi = Gp[0]; gf = Gp[512]; gg_ = Gp[1024]; go = Gp[1536];
    }

    for (int t = 0; t < 48; ++t) {
        const float* h_in = (t == 0) ? dh : ((t & 1) ? hq : hp);
        float* h_out = (t & 1) ? hp : hq;
        const float4* hin4 = reinterpret_cast<const float4*>(h_in);
#pragma unroll
        for (int i = 0; i < 8; ++i) h4[tid + i * 256] = __ldcg(hin4 + tid + i * 256);
        __syncthreads();

        float acc[16];
#pragma unroll
        for (int i = 0; i < 16; ++i) acc[i] = 0.f;
#pragma unroll
        for (int b = 0; b < 16; ++b) {
            const float4* hb = &h4[b * 128 + kc * 8];
#pragma unroll
            for (int i = 0; i < 8; ++i) {
                float4 hv = hb[i];
                acc[b] += w[i].x * hv.x + w[i].y * hv.y + w[i].z * hv.z + w[i].w * hv.w;
            }
        }
        __syncthreads();                        // h4 reads done; safe to overlay red

        float4* redv = reinterpret_cast<float4*>(red);
        int rb = (kc * 16 + rid) * 4;
        redv[rb + 0] = make_float4(acc[0],  acc[1],  acc[2],  acc[3]);
        redv[rb + 1] = make_float4(acc[4],  acc[5],  acc[6],  acc[7]);
        redv[rb + 2] = make_float4(acc[8],  acc[9],  acc[10], acc[11]);
        redv[rb + 3] = make_float4(acc[12], acc[13], acc[14], acc[15]);
        __syncthreads();

        float s = 0.f;
#pragma unroll
        for (int q = 0; q < 16; ++q) s += red[q * 256 + tid];
        gsum[tid] = s;
        __syncthreads();

        if (tid < 64) {
            float ip = gsum[tid]       + gi;
            float fp = gsum[64 + tid]  + gf;
            float gp = gsum[128 + tid] + gg_;
            float op = gsum[192 + tid] + go;
            float c = sigm(fp) * c_sm[tid] + sigm(ip) * tanhf(gp);
            c_sm[tid] = c;
            float h = sigm(op) * tanhf(c);
            h_out[ub * 512 + ujg] = h;
            ds_out[(size_t)(t * 16 + ub) * 512 + ujg] = h;
        }
        if (t < 47) {
            if (tid < 64) {                      // prefetch next step's gates
                const float* Gp = G + (size_t)((t + 1) * 16 + ub) * 2048 + ujg;
                gi = Gp[0]; gf = Gp[512]; gg_ = Gp[1024]; go = Gp[1536];
            }
            gbar(ls);
        }
    }
}

// ======================= persistent encoder layer =======================
// 128 CTAs x 256 threads. dir = bx>>6; CTA owns 4 j of 256 (x 4 gates).
__global__ __launch_bounds__(256, 1) void enc_layer_k(
    const float* __restrict__ Whh,             // (2,1024,256)
    const float* __restrict__ G, float* __restrict__ xs_out,
    float* __restrict__ hp, float* __restrict__ hq,
    float* __restrict__ dh, float* __restrict__ dc) {
    __shared__ float4 h4[1024];                // 16KB
    __shared__ float red[4096];
    __shared__ float gsum[256];
    __shared__ float c_sm[64];
    __shared__ unsigned s_sense;

    int tid = threadIdx.x;
    int kc = tid >> 4;
    int rid = tid & 15;
    int g = rid >> 2, jj = rid & 3;
    int dir = blockIdx.x >> 6;
    int j0 = (blockIdx.x & 63) * 4;
    int jg = j0 + jj;
    int row = g * 256 + jg;

    const float4* wp = reinterpret_cast<const float4*>(
        Whh + (size_t)dir * 1024 * 256 + (size_t)row * 256 + kc * 16);
    float4 w[4];
#pragma unroll
    for (int i = 0; i < 4; ++i) w[i] = wp[i];

    int ujj = tid >> 4, ub = tid & 15;          // valid when tid<64
    int ujg = j0 + ujj;
    if (tid < 64) c_sm[tid] = 0.f;
    if (tid == 0) {
        unsigned v;
        asm volatile("ld.relaxed.gpu.u32 %0, [%1];" : "=r"(v) : "l"(&g_sync[0]) : "memory");
        s_sense = v;
    }
    __syncthreads();
    unsigned ls = s_sense;

    float gi = 0.f, gf = 0.f, gg_ = 0.f, go = 0.f;
    if (tid < 64) {
        int tt0 = dir ? 47 : 0;
        const float* Gp = G + (size_t)(tt0 * 16 + ub) * 2048 + dir * 1024 + ujg;
        gi = Gp[0]; gf = Gp[256]; gg_ = Gp[512]; go = Gp[768];
    }

    for (int t = 0; t < 48; ++t) {
        int tt = dir ? (47 - t) : t;
        float* h_out = (t & 1) ? hp : hq;

        float s = 0.f;
        if (t > 0) {
            const float* h_in = (t & 1) ? hq : hp;
            const float4* hin4 = reinterpret_cast<const float4*>(h_in + dir * 4096);
#pragma unroll
            for (int i = 0; i < 4; ++i) h4[tid + i * 256] = __ldcg(hin4 + tid + i * 256);
            __syncthreads();

            float acc[16];
#pragma unroll
            for (int i = 0; i < 16; ++i) acc[i] = 0.f;
#pragma unroll
            for (int b = 0; b < 16; ++b) {
                const float4* hb = &h4[b * 64 + kc * 4];
#pragma unroll
                for (int i = 0; i < 4; ++i) {
                    float4 hv = hb[i];
                    acc[b] += w[i].x * hv.x + w[i].y * hv.y + w[i].z * hv.z + w[i].w * hv.w;
                }
            }
            float4* redv = reinterpret_cast<float4*>(red);
            int rb = (kc * 16 + rid) * 4;
            redv[rb + 0] = make_float4(acc[0],  acc[1],  acc[2],  acc[3]);
            redv[rb + 1] = make_float4(acc[4],  acc[5],  acc[6],  acc[7]);
            redv[rb + 2] = make_float4(acc[8],  acc[9],  acc[10], acc[11]);
            redv[rb + 3] = make_float4(acc[12], acc[13], acc[14], acc[15]);
            __syncthreads();
#pragma unroll
            for (int q = 0; q < 16; ++q) s += red[q * 256 + tid];
        }
        gsum[tid] = s;
        __syncthreads();

        if (tid < 64) {
            float ip = gsum[tid]       + gi;
            float fp = gsum[64 + tid]  + gf;
            float gp = gsum[128 + tid] + gg_;
            float op = gsum[192 + tid] + go;
            float c = sigm(fp) * c_sm[tid] + sigm(ip) * tanhf(gp);
            c_sm[tid] = c;
            float h = sigm(op) * tanhf(c);
            h_out[dir * 4096 + ub * 256 + ujg] = h;
            xs_out[(size_t)(tt * 16 + ub) * 512 + dir * 256 + ujg] = h;
            if (t == 47) {
                dh[ub * 512 + dir * 256 + ujg] = h;
                dc[ub * 512 + dir * 256 + ujg] = c;
            }
        }
        if (t < 47) {
            if (tid < 64) {                      // prefetch next step's gates
                int ttn = dir ? (47 - (t + 1)) : (t + 1);
                const float* Gp = G + (size_t)(ttn * 16 + ub) * 2048 + dir * 1024 + ujg;
                gi = Gp[0]; gf = Gp[256]; gg_ = Gp[512]; go = Gp[768];
            }
            gbar(ls);
        }
    }
}

// ---------------- launch sequence ----------------
extern "C" void kernel_launch(void* const* d_in, const int* in_sizes, int n_in,
                              void* d_out, int out_size) {
    const int*   x        = (const int*)d_in[0];
    const int*   y        = (const int*)d_in[1];
    const float* enc_emb  = (const float*)d_in[2];
    const float* enc_Wih  = (const float*)d_in[3];
    const float* enc_Whh  = (const float*)d_in[4];
    const float* enc_b    = (const float*)d_in[5];
    const float* dec_emb  = (const float*)d_in[6];
    const float* dec_Wih  = (const float*)d_in[7];
    const float* dec_Whh  = (const float*)d_in[8];
    const float* dec_b    = (const float*)d_in[9];
    const float* lin_W    = (const float*)d_in[10];
    const float* lin_b    = (const float*)d_in[11];
    float* out = (float*)d_out;

    float *act0, *act1, *G, *hp, *hq, *dh, *dc;
    cudaGetSymbolAddress((void**)&act0, g_act0);
    cudaGetSymbolAddress((void**)&act1, g_act1);
    cudaGetSymbolAddress((void**)&G,    g_G);
    cudaGetSymbolAddress((void**)&hp,   g_hping);
    cudaGetSymbolAddress((void**)&hq,   g_hpong);
    cudaGetSymbolAddress((void**)&dh,   g_dech0);
    cudaGetSymbolAddress((void**)&dc,   g_decc0);
    float* bufs[2] = {act0, act1};

    // ---- encoder ----
    embed_k<<<768, 128>>>(enc_emb, x, bufs[0]);
    int p = 0;
    for (int l = 0; l < NL; ++l) {
        gemm_k<<<dim3(32, 12), 256>>>(bufs[p], enc_Wih + (size_t)l * 1024 * 1024,
                                      enc_b + l * 2048, G,
                                      (size_t)2048, (size_t)32768, (size_t)1);
        enc_layer_k<<<128, 256>>>(enc_Whh + (size_t)l * 2 * 1024 * 256, G,
                                  bufs[1 - p], hp, hq,
                                  dh + l * 8192, dc + l * 8192);
        p ^= 1;
    }

    // ---- decoder ----
    embed_k<<<768, 128>>>(dec_emb, y, bufs[p]);
    for (int l = 0; l < NL; ++l) {
        gemm_k<<<dim3(32, 12), 256>>>(bufs[p], dec_Wih + (size_t)l * 2048 * 512,
                                      dec_b + l * 2048, G,
                                      (size_t)2048, (size_t)32768, (size_t)1);
        dec_layer_k<<<128, 256>>>(dec_Whh + (size_t)l * 2048 * 512, G,
                                  bufs[1 - p], hp, hq,
                                  dh + l * 8192, dc + l * 8192);
        p ^= 1;
    }

    // ---- final projection: out[b][v][t] ----
    gemm_k<<<dim3(500, 12), 256>>>(bufs[p], lin_W, lin_b, out,
                                   (size_t)VOUT * 48, (size_t)1, (size_t)48);
}

// round 6
// speedup vs baseline: 1.6032x; 1.6032x over previous
#include <cuda_runtime.h>
#include <math.h>

#define S 48
#define BATCH 16
#define HID 512
#define HDIR 256
#define NL 16
#define M_ROWS 768            // S*BATCH
#define VOUT 32000

// ---------------- device scratch (static, no allocation) ----------------
__device__ float g_act0[M_ROWS * HID];
__device__ float g_act1[M_ROWS * HID];
__device__ float g_G[M_ROWS * 2048];
__device__ float g_hping[8192];
__device__ float g_hpong[8192];
__device__ float g_dech0[NL * 8192];
__device__ float g_decc0[NL * 8192];
// per-domain sync: dom d uses cnt=g_syn[d*512], sense=g_syn[d*512+64]
__device__ unsigned g_syn[1024];

#define CLUSTER_ARRIVE() asm volatile("barrier.cluster.arrive.aligned;" ::: "memory")
#define CLUSTER_WAIT()   asm volatile("barrier.cluster.wait.aligned;" ::: "memory")

__device__ __forceinline__ unsigned ctarank_in_cluster() {
    unsigned r;
    asm("mov.u32 %0, %%cluster_ctarank;" : "=r"(r));
    return r;
}

// global handshake among cluster leaders only (monotonic epoch, wrap-safe)
__device__ __forceinline__ void leader_bar(unsigned* cnt, volatile unsigned* sense,
                                           unsigned tgt, unsigned nlead) {
    unsigned old = atomicAdd(cnt, 1u);
    if (old == nlead - 1u) {
        *(volatile unsigned*)cnt = 0u;
        __threadfence();
        *sense = tgt;
    } else {
        int spin = 0;
        while ((int)(*sense - tgt) < 0) {
            if (++spin > 64) __nanosleep(32);
        }
    }
}

// hierarchical grid barrier: HW cluster barrier + 8/16-leader global handshake
__device__ __forceinline__ void grid_bar_h(unsigned crank, unsigned& tgt,
                                           unsigned* cnt, volatile unsigned* sense,
                                           unsigned nlead) {
    __syncthreads();
    if (threadIdx.x == 0) __threadfence();   // drain this CTA's stores to L2
    CLUSTER_ARRIVE();
    CLUSTER_WAIT();
    if (crank == 0u && threadIdx.x == 0) {
        ++tgt;
        leader_bar(cnt, sense, tgt, nlead);
    }
    CLUSTER_ARRIVE();                        // leader arrives only after global release
    CLUSTER_WAIT();
}

// ---------------- embedding gather ----------------
__global__ void embed_k(const float* __restrict__ emb, const int* __restrict__ ids,
                        float* __restrict__ out) {
    int tb = blockIdx.x;            // t*16+b
    int t = tb >> 4, b = tb & 15;
    int id = ids[b * S + t];
    const float4* src = reinterpret_cast<const float4*>(emb) + (size_t)id * (HID / 4);
    float4* dst = reinterpret_cast<float4*>(out) + (size_t)tb * (HID / 4);
    dst[threadIdx.x] = src[threadIdx.x];
}

// ---------------- C[m][n] = A[m][:512] . W[n][:512] + bias[n], M=768, K=512 ----------------
__global__ __launch_bounds__(256) void gemm_k(
    const float* __restrict__ A, const float* __restrict__ W,
    const float* __restrict__ bias, float* __restrict__ C,
    size_t sB, size_t sT, size_t sN) {
    __shared__ float4 smem4[(16 * 68 * 2) / 4];
    float* As = (float*)smem4;
    float* Ws = As + 16 * 68;
    int tid = threadIdx.x;
    int tx = tid & 15, ty = tid >> 4;
    int n0 = blockIdx.x * 64, m0 = blockIdx.y * 64;
    int r = tid >> 2, kq = (tid & 3) * 4;

    float acc[16];
#pragma unroll
    for (int i = 0; i < 16; ++i) acc[i] = 0.f;

    for (int k0 = 0; k0 < 512; k0 += 16) {
        float4 a = *reinterpret_cast<const float4*>(A + (size_t)(m0 + r) * 512 + k0 + kq);
        float4 w = *reinterpret_cast<const float4*>(W + (size_t)(n0 + r) * 512 + k0 + kq);
        As[(kq + 0) * 68 + r] = a.x; As[(kq + 1) * 68 + r] = a.y;
        As[(kq + 2) * 68 + r] = a.z; As[(kq + 3) * 68 + r] = a.w;
        Ws[(kq + 0) * 68 + r] = w.x; Ws[(kq + 1) * 68 + r] = w.y;
        Ws[(kq + 2) * 68 + r] = w.z; Ws[(kq + 3) * 68 + r] = w.w;
        __syncthreads();
#pragma unroll
        for (int kk = 0; kk < 16; ++kk) {
            float4 av = *reinterpret_cast<const float4*>(&As[kk * 68 + ty * 4]);
            float4 wv = *reinterpret_cast<const float4*>(&Ws[kk * 68 + tx * 4]);
            acc[0]  += av.x * wv.x; acc[1]  += av.x * wv.y; acc[2]  += av.x * wv.z; acc[3]  += av.x * wv.w;
            acc[4]  += av.y * wv.x; acc[5]  += av.y * wv.y; acc[6]  += av.y * wv.z; acc[7]  += av.y * wv.w;
            acc[8]  += av.z * wv.x; acc[9]  += av.z * wv.y; acc[10] += av.z * wv.z; acc[11] += av.z * wv.w;
            acc[12] += av.w * wv.x; acc[13] += av.w * wv.y; acc[14] += av.w * wv.z; acc[15] += av.w * wv.w;
        }
        __syncthreads();
    }
#pragma unroll
    for (int i = 0; i < 4; ++i) {
        int m = m0 + ty * 4 + i;
        int b = m & 15, t = m >> 4;
#pragma unroll
        for (int jx = 0; jx < 4; ++jx) {
            int n = n0 + tx * 4 + jx;
            C[(size_t)b * sB + (size_t)t * sT + (size_t)n * sN] = acc[i * 4 + jx] + bias[n];
        }
    }
}

__device__ __forceinline__ float sigm(float x) { return 1.f / (1.f + expf(-x)); }

// ======================= persistent decoder layer =======================
// 128 CTAs (16 clusters of 8) x 256 threads. CTA owns 4 j (x 4 gates).
__global__ __launch_bounds__(256, 1) __cluster_dims__(8, 1, 1) void dec_layer_k(
    const float* __restrict__ Whh,             // (2048,512)
    const float* __restrict__ G, float* __restrict__ ds_out,
    float* __restrict__ hp, float* __restrict__ hq,
    const float* __restrict__ dh, const float* __restrict__ dc) {
    __shared__ float4 h4[2048];                // 32KB; overlaid by red/gsum after use
    __shared__ float c_sm[64];
    float* red = reinterpret_cast<float*>(h4); // [kc*256 + rid*16 + b]
    float* gsum = red + 4096;                  // 256 floats

    int tid = threadIdx.x;
    int kc = tid >> 4;
    int rid = tid & 15;
    int g = rid >> 2, jj = rid & 3;
    int j0 = blockIdx.x * 4;
    int row = g * 512 + j0 + jj;
    unsigned crank = ctarank_in_cluster();

    const float4* wp = reinterpret_cast<const float4*>(Whh + (size_t)row * 512 + kc * 32);
    float4 w[8];
#pragma unroll
    for (int i = 0; i < 8; ++i) w[i] = wp[i];

    int ujj = tid >> 4, ub = tid & 15;          // valid when tid<64
    int ujg = j0 + ujj;
    if (tid < 64) c_sm[tid] = dc[ub * 512 + ujg];

    unsigned* cnt_ = &g_syn[0];
    volatile unsigned* sense_ = (volatile unsigned*)&g_syn[64];
    unsigned tgt = 0;
    if (crank == 0u && tid == 0) tgt = *sense_;     // epoch base (persists across kernels)

    float gi = 0.f, gf = 0.f, gg_ = 0.f, go = 0.f;
    if (tid < 64) {
        const float* Gp = G + (size_t)ub * 2048 + ujg;    // t = 0
        gi = Gp[0]; gf = Gp[512]; gg_ = Gp[1024]; go = Gp[1536];
    }
    __syncthreads();

    for (int t = 0; t < 48; ++t) {
        const float* h_in = (t == 0) ? dh : ((t & 1) ? hq : hp);
        float* h_out = (t & 1) ? hp : hq;
        const float4* hin4 = reinterpret_cast<const float4*>(h_in);
#pragma unroll
        for (int i = 0; i < 8; ++i) h4[tid + i * 256] = __ldcg(hin4 + tid + i * 256);
        __syncthreads();

        float acc[16];
#pragma unroll
        for (int i = 0; i < 16; ++i) acc[i] = 0.f;
#pragma unroll
        for (int b = 0; b < 16; ++b) {
            const float4* hb = &h4[b * 128 + kc * 8];
#pragma unroll
            for (int i = 0; i < 8; ++i) {
                float4 hv = hb[i];
                acc[b] += w[i].x * hv.x + w[i].y * hv.y + w[i].z * hv.z + w[i].w * hv.w;
            }
        }
        __syncthreads();                        // h4 reads done; safe to overlay red

        float4* redv = reinterpret_cast<float4*>(red);
        int rb = (kc * 16 + rid) * 4;
        redv[rb + 0] = make_float4(acc[0],  acc[1],  acc[2],  acc[3]);
        redv[rb + 1] = make_float4(acc[4],  acc[5],  acc[6],  acc[7]);
        redv[rb + 2] = make_float4(acc[8],  acc[9],  acc[10], acc[11]);
        redv[rb + 3] = make_float4(acc[12], acc[13], acc[14], acc[15]);
        __syncthreads();

        float s = 0.f;
#pragma unroll
        for (int q = 0; q < 16; ++q) s += red[q * 256 + tid];
        gsum[tid] = s;
        __syncthreads();

        if (tid < 64) {
            float ip = gsum[tid]       + gi;
            float fp = gsum[64 + tid]  + gf;
            float gp = gsum[128 + tid] + gg_;
            float op = gsum[192 + tid] + go;
            float c = sigm(fp) * c_sm[tid] + sigm(ip) * tanhf(gp);
            c_sm[tid] = c;
            float h = sigm(op) * tanhf(c);
            h_out[ub * 512 + ujg] = h;
            ds_out[(size_t)(t * 16 + ub) * 512 + ujg] = h;
        }
        if (t < 47) {
            if (tid < 64) {                      // prefetch next step's gates
                const float* Gp = G + (size_t)((t + 1) * 16 + ub) * 2048 + ujg;
                gi = Gp[0]; gf = Gp[512]; gg_ = Gp[1024]; go = Gp[1536];
            }
            grid_bar_h(crank, tgt, cnt_, sense_, 16u);
        }
    }
}

// ======================= persistent encoder layer =======================
// 128 CTAs (16 clusters of 8) x 256 threads. dir = bx>>6 -> independent sync domain.
__global__ __launch_bounds__(256, 1) __cluster_dims__(8, 1, 1) void enc_layer_k(
    const float* __restrict__ Whh,             // (2,1024,256)
    const float* __restrict__ G, float* __restrict__ xs_out,
    float* __restrict__ hp, float* __restrict__ hq,
    float* __restrict__ dh, float* __restrict__ dc) {
    __shared__ float4 h4[1024];                // 16KB
    __shared__ float red[4096];
    __shared__ float gsum[256];
    __shared__ float c_sm[64];

    int tid = threadIdx.x;
    int kc = tid >> 4;
    int rid = tid & 15;
    int g = rid >> 2, jj = rid & 3;
    int dir = blockIdx.x >> 6;
    int j0 = (blockIdx.x & 63) * 4;
    int jg = j0 + jj;
    int row = g * 256 + jg;
    unsigned crank = ctarank_in_cluster();

    const float4* wp = reinterpret_cast<const float4*>(
        Whh + (size_t)dir * 1024 * 256 + (size_t)row * 256 + kc * 16);
    float4 w[4];
#pragma unroll
    for (int i = 0; i < 4; ++i) w[i] = wp[i];

    int ujj = tid >> 4, ub = tid & 15;          // valid when tid<64
    int ujg = j0 + ujj;
    if (tid < 64) c_sm[tid] = 0.f;

    unsigned* cnt_ = &g_syn[dir * 512];
    volatile unsigned* sense_ = (volatile unsigned*)&g_syn[dir * 512 + 64];
    unsigned tgt = 0;
    if (crank == 0u && tid == 0) tgt = *sense_;

    float gi = 0.f, gf = 0.f, gg_ = 0.f, go = 0.f;
    if (tid < 64) {
        int tt0 = dir ? 47 : 0;
        const float* Gp = G + (size_t)(tt0 * 16 + ub) * 2048 + dir * 1024 + ujg;
        gi = Gp[0]; gf = Gp[256]; gg_ = Gp[512]; go = Gp[768];
    }
    __syncthreads();

    for (int t = 0; t < 48; ++t) {
        int tt = dir ? (47 - t) : t;
        float* h_out = (t & 1) ? hp : hq;

        float s = 0.f;
        if (t > 0) {
            const float* h_in = (t & 1) ? hq : hp;
            const float4* hin4 = reinterpret_cast<const float4*>(h_in + dir * 4096);
#pragma unroll
            for (int i = 0; i < 4; ++i) h4[tid + i * 256] = __ldcg(hin4 + tid + i * 256);
            __syncthreads();

            float acc[16];
#pragma unroll
            for (int i = 0; i < 16; ++i) acc[i] = 0.f;
#pragma unroll
            for (int b = 0; b < 16; ++b) {
                const float4* hb = &h4[b * 64 + kc * 4];
#pragma unroll
                for (int i = 0; i < 4; ++i) {
                    float4 hv = hb[i];
                    acc[b] += w[i].x * hv.x + w[i].y * hv.y + w[i].z * hv.z + w[i].w * hv.w;
                }
            }
            float4* redv = reinterpret_cast<float4*>(red);
            int rb = (kc * 16 + rid) * 4;
            redv[rb + 0] = make_float4(acc[0],  acc[1],  acc[2],  acc[3]);
            redv[rb + 1] = make_float4(acc[4],  acc[5],  acc[6],  acc[7]);
            redv[rb + 2] = make_float4(acc[8],  acc[9],  acc[10], acc[11]);
            redv[rb + 3] = make_float4(acc[12], acc[13], acc[14], acc[15]);
            __syncthreads();
#pragma unroll
            for (int q = 0; q < 16; ++q) s += red[q * 256 + tid];
        }
        gsum[tid] = s;
        __syncthreads();

        if (tid < 64) {
            float ip = gsum[tid]       + gi;
            float fp = gsum[64 + tid]  + gf;
            float gp = gsum[128 + tid] + gg_;
            float op = gsum[192 + tid] + go;
            float c = sigm(fp) * c_sm[tid] + sigm(ip) * tanhf(gp);
            c_sm[tid] = c;
            float h = sigm(op) * tanhf(c);
            h_out[dir * 4096 + ub * 256 + ujg] = h;
            xs_out[(size_t)(tt * 16 + ub) * 512 + dir * 256 + ujg] = h;
            if (t == 47) {
                dh[ub * 512 + dir * 256 + ujg] = h;
                dc[ub * 512 + dir * 256 + ujg] = c;
            }
        }
        if (t < 47) {
            if (tid < 64) {                      // prefetch next step's gates
                int ttn = dir ? (47 - (t + 1)) : (t + 1);
                const float* Gp = G + (size_t)(ttn * 16 + ub) * 2048 + dir * 1024 + ujg;
                gi = Gp[0]; gf = Gp[256]; gg_ = Gp[512]; go = Gp[768];
            }
            grid_bar_h(crank, tgt, cnt_, sense_, 8u);
        }
    }
}

// ---------------- launch sequence ----------------
extern "C" void kernel_launch(void* const* d_in, const int* in_sizes, int n_in,
                              void* d_out, int out_size) {
    const int*   x        = (const int*)d_in[0];
    const int*   y        = (const int*)d_in[1];
    const float* enc_emb  = (const float*)d_in[2];
    const float* enc_Wih  = (const float*)d_in[3];
    const float* enc_Whh  = (const float*)d_in[4];
    const float* enc_b    = (const float*)d_in[5];
    const float* dec_emb  = (const float*)d_in[6];
    const float* dec_Wih  = (const float*)d_in[7];
    const float* dec_Whh  = (const float*)d_in[8];
    const float* dec_b    = (const float*)d_in[9];
    const float* lin_W    = (const float*)d_in[10];
    const float* lin_b    = (const float*)d_in[11];
    float* out = (float*)d_out;

    float *act0, *act1, *G, *hp, *hq, *dh, *dc;
    cudaGetSymbolAddress((void**)&act0, g_act0);
    cudaGetSymbolAddress((void**)&act1, g_act1);
    cudaGetSymbolAddress((void**)&G,    g_G);
    cudaGetSymbolAddress((void**)&hp,   g_hping);
    cudaGetSymbolAddress((void**)&hq,   g_hpong);
    cudaGetSymbolAddress((void**)&dh,   g_dech0);
    cudaGetSymbolAddress((void**)&dc,   g_decc0);
    float* bufs[2] = {act0, act1};

    // ---- encoder ----
    embed_k<<<768, 128>>>(enc_emb, x, bufs[0]);
    int p = 0;
    for (int l = 0; l < NL; ++l) {
        gemm_k<<<dim3(32, 12), 256>>>(bufs[p], enc_Wih + (size_t)l * 1024 * 1024,
                                      enc_b + l * 2048, G,
                                      (size_t)2048, (size_t)32768, (size_t)1);
        enc_layer_k<<<128, 256>>>(enc_Whh + (size_t)l * 2 * 1024 * 256, G,
                                  bufs[1 - p], hp, hq,
                                  dh + l * 8192, dc + l * 8192);
        p ^= 1;
    }

    // ---- decoder ----
    embed_k<<<768, 128>>>(dec_emb, y, bufs[p]);
    for (int l = 0; l < NL; ++l) {
        gemm_k<<<dim3(32, 12), 256>>>(bufs[p], dec_Wih + (size_t)l * 2048 * 512,
                                      dec_b + l * 2048, G,
                                      (size_t)2048, (size_t)32768, (size_t)1);
        dec_layer_k<<<128, 256>>>(dec_Whh + (size_t)l * 2048 * 512, G,
                                  bufs[1 - p], hp, hq,
                                  dh + l * 8192, dc + l * 8192);
        p ^= 1;
    }

    // ---- final projection: out[b][v][t] ----
    gemm_k<<<dim3(500, 12), 256>>>(bufs[p], lin_W, lin_b, out,
                                   (size_t)VOUT * 48, (size_t)1, (size_t)48);
}